// round 2
// baseline (speedup 1.0000x reference)
#include <cuda_runtime.h>
#include <cuda_bf16.h>

// GlobalAttentionLayer, single fused pass (R2).
// pooled[b] = sum_n e^{g_n} * (states_n @ Wo + bo) / (sum_n e^{g_n} + eps)
//
// R2 changes vs R1:
//  - only the gate dot product is warp-reduced per node (5 shfl instead of 15);
//    output-projection partials stay per-lane, scaled by e, reduced once per
//    segment flush:  sum_n e_n*(p0_n + bo0) = sum_lanes(sum_n e_n*p0_{n,l}) + bo0*sum_n e_n
//  - x4 unrolled main loop with all 8 LDG.128 batched up front (MLP ~8/warp)
//  - packed f32x2 FMA (sm_103a) for dot products and value accumulation
//
// Inputs (metadata order):
//   d_in[0] states  float32 [N, 256]
//   d_in[1] seg_ids int32   [N]   (sorted)
//   d_in[2] Wg      float32 [256, 1]
//   d_in[3] bg      float32 [1]
//   d_in[4] Wo      float32 [256, 2]
//   d_in[5] bo      float32 [2]
// Output: float32 [B, 2], B = out_size/2

#define NBLOCKS  592
#define NTHREADS 256
#define MAXB     1024

typedef unsigned long long ull;

__device__ float g_accS [MAXB];
__device__ float g_accV0[MAXB];
__device__ float g_accV1[MAXB];

__device__ __forceinline__ ull pack2(float lo, float hi) {
    ull r; asm("mov.b64 %0, {%1, %2};" : "=l"(r) : "f"(lo), "f"(hi)); return r;
}
__device__ __forceinline__ void unpack2(ull v, float& lo, float& hi) {
    asm("mov.b64 {%0, %1}, %2;" : "=f"(lo), "=f"(hi) : "l"(v));
}
__device__ __forceinline__ ull fma2(ull a, ull b, ull c) {
    ull d; asm("fma.rn.f32x2 %0, %1, %2, %3;" : "=l"(d) : "l"(a), "l"(b), "l"(c)); return d;
}

__global__ void ga_zero(int B) {
    int i = blockIdx.x * blockDim.x + threadIdx.x;
    if (i < B) {
        g_accS [i] = 0.0f;
        g_accV0[i] = 0.0f;
        g_accV1[i] = 0.0f;
    }
}

__global__ __launch_bounds__(NTHREADS) void ga_main(
    const float* __restrict__ states,
    const int*   __restrict__ seg,
    const float* __restrict__ Wg,
    const float* __restrict__ bg,
    const float* __restrict__ Wo,
    const float* __restrict__ bo,
    int N)
{
    const int lane   = threadIdx.x & 31;
    const int gwarp  = (blockIdx.x * blockDim.x + threadIdx.x) >> 5;
    const int nwarps = (gridDim.x * blockDim.x) >> 5;
    const int chunk  = (N + nwarps - 1) / nwarps;
    const int start  = gwarp * chunk;
    const int end    = min(start + chunk, N);
    if (start >= end) return;

    // Per-lane slice: columns [lane*8, lane*8+8), packed as 4 x f32x2
    const int c0 = lane * 8;
    ull wgp[4], wo0p[4], wo1p[4];
#pragma unroll
    for (int j = 0; j < 4; j++) {
        wgp [j] = pack2(Wg[c0 + 2*j],           Wg[c0 + 2*j + 1]);
        wo0p[j] = pack2(Wo[(c0 + 2*j) * 2 + 0], Wo[(c0 + 2*j + 1) * 2 + 0]);
        wo1p[j] = pack2(Wo[(c0 + 2*j) * 2 + 1], Wo[(c0 + 2*j + 1) * 2 + 1]);
    }
    const float bgv = bg[0];
    const float bo0 = bo[0];
    const float bo1 = bo[1];

    const float4* base = reinterpret_cast<const float4*>(states);

    int cur   = seg[start];
    float aS  = 0.0f;        // sum of e (uniform across lanes)
    ull  aV0p = 0ULL;        // per-lane packed sum of e * p0_lane
    ull  aV1p = 0ULL;

    int n = start;

#define FLUSH(SEGID)                                                        \
    do {                                                                    \
        float _lo, _hi, _v0, _v1;                                           \
        unpack2(aV0p, _lo, _hi); _v0 = _lo + _hi;                           \
        unpack2(aV1p, _lo, _hi); _v1 = _lo + _hi;                           \
        _Pragma("unroll")                                                   \
        for (int _o = 16; _o; _o >>= 1) {                                   \
            _v0 += __shfl_xor_sync(0xFFFFFFFFu, _v0, _o);                   \
            _v1 += __shfl_xor_sync(0xFFFFFFFFu, _v1, _o);                   \
        }                                                                   \
        if (lane == 0) {                                                    \
            atomicAdd(&g_accS [SEGID], aS);                                 \
            atomicAdd(&g_accV0[SEGID], fmaf(bo0, aS, _v0));                 \
            atomicAdd(&g_accV1[SEGID], fmaf(bo1, aS, _v1));                 \
        }                                                                   \
        aS = 0.0f; aV0p = 0ULL; aV1p = 0ULL;                                \
    } while (0)

    // ---- main loop: 4 nodes per iteration, loads batched up front ----
    for (; n + 4 <= end; n += 4) {
        float4 xa[4], xb[4];
        int    sv[4];
#pragma unroll
        for (int k = 0; k < 4; k++) {
            const float4* row = base + (size_t)(n + k) * 64 + lane * 2;
            xa[k] = __ldcs(row);
            xb[k] = __ldcs(row + 1);
            sv[k] = seg[n + k];
        }

        float gk[4];
        ull   p0p[4], p1p[4];
#pragma unroll
        for (int k = 0; k < 4; k++) {
            ull x0 = pack2(xa[k].x, xa[k].y);
            ull x1 = pack2(xa[k].z, xa[k].w);
            ull x2 = pack2(xb[k].x, xb[k].y);
            ull x3 = pack2(xb[k].z, xb[k].w);

            ull pg = fma2(x0, wgp[0], 0ULL);
            pg     = fma2(x1, wgp[1], pg);
            pg     = fma2(x2, wgp[2], pg);
            pg     = fma2(x3, wgp[3], pg);

            ull p0 = fma2(x0, wo0p[0], 0ULL);
            p0     = fma2(x1, wo0p[1], p0);
            p0     = fma2(x2, wo0p[2], p0);
            p0     = fma2(x3, wo0p[3], p0);
            p0p[k] = p0;

            ull p1 = fma2(x0, wo1p[0], 0ULL);
            p1     = fma2(x1, wo1p[1], p1);
            p1     = fma2(x2, wo1p[2], p1);
            p1     = fma2(x3, wo1p[3], p1);
            p1p[k] = p1;

            float lo, hi;
            unpack2(pg, lo, hi);
            gk[k] = lo + hi;
        }

        // 4 independent butterfly chains (overlap the 26-cyc shfl latency)
#pragma unroll
        for (int off = 16; off; off >>= 1) {
#pragma unroll
            for (int k = 0; k < 4; k++)
                gk[k] += __shfl_xor_sync(0xFFFFFFFFu, gk[k], off);
        }

#pragma unroll
        for (int k = 0; k < 4; k++) {
            float e = __expf(gk[k] + bgv);
            if (sv[k] != cur) {          // rare (B=64 boundaries in 1M nodes)
                FLUSH(cur);
                cur = sv[k];
            }
            aS += e;
            ull ep = pack2(e, e);
            aV0p = fma2(ep, p0p[k], aV0p);
            aV1p = fma2(ep, p1p[k], aV1p);
        }
    }

    // ---- tail (<4 nodes) ----
    for (; n < end; n++) {
        const float4* row = base + (size_t)n * 64 + lane * 2;
        float4 xa = __ldcs(row);
        float4 xb = __ldcs(row + 1);
        int s = seg[n];

        ull x0 = pack2(xa.x, xa.y), x1 = pack2(xa.z, xa.w);
        ull x2 = pack2(xb.x, xb.y), x3 = pack2(xb.z, xb.w);

        ull pg = fma2(x0, wgp[0], 0ULL);
        pg     = fma2(x1, wgp[1], pg);
        pg     = fma2(x2, wgp[2], pg);
        pg     = fma2(x3, wgp[3], pg);
        ull p0 = fma2(x0, wo0p[0], 0ULL);
        p0     = fma2(x1, wo0p[1], p0);
        p0     = fma2(x2, wo0p[2], p0);
        p0     = fma2(x3, wo0p[3], p0);
        ull p1 = fma2(x0, wo1p[0], 0ULL);
        p1     = fma2(x1, wo1p[1], p1);
        p1     = fma2(x2, wo1p[2], p1);
        p1     = fma2(x3, wo1p[3], p1);

        float lo, hi;
        unpack2(pg, lo, hi);
        float g = lo + hi;
#pragma unroll
        for (int off = 16; off; off >>= 1)
            g += __shfl_xor_sync(0xFFFFFFFFu, g, off);

        float e = __expf(g + bgv);
        if (s != cur) {
            FLUSH(cur);
            cur = s;
        }
        aS += e;
        ull ep = pack2(e, e);
        aV0p = fma2(ep, p0, aV0p);
        aV1p = fma2(ep, p1, aV1p);
    }

    FLUSH(cur);
#undef FLUSH
}

__global__ void ga_finalize(float* __restrict__ out, int B) {
    int b = blockIdx.x * blockDim.x + threadIdx.x;
    if (b < B) {
        float d = g_accS[b] + 1e-16f;
        out[2 * b + 0] = g_accV0[b] / d;
        out[2 * b + 1] = g_accV1[b] / d;
    }
}

extern "C" void kernel_launch(void* const* d_in, const int* in_sizes, int n_in,
                              void* d_out, int out_size)
{
    const float* states = (const float*)d_in[0];
    const int*   seg    = (const int*)  d_in[1];
    const float* Wg     = (const float*)d_in[2];
    const float* bg     = (const float*)d_in[3];
    const float* Wo     = (const float*)d_in[4];
    const float* bo     = (const float*)d_in[5];
    float*       out    = (float*)d_out;

    const int N = in_sizes[1];
    const int B = out_size / 2;

    ga_zero<<<(B + 255) / 256, 256>>>(B);
    ga_main<<<NBLOCKS, NTHREADS>>>(states, seg, Wg, bg, Wo, bo, N);
    ga_finalize<<<(B + 255) / 256, 256>>>(out, B);
}

// round 3
// speedup vs baseline: 1.2126x; 1.2126x over previous
#include <cuda_runtime.h>
#include <cuda_bf16.h>

// GlobalAttentionLayer, single fused pass (R3).
// pooled[b] = sum_n e^{g_n} * (states_n @ Wo + bo) / (sum_n e^{g_n} + eps)
//
// R3 = R1 skeleton (scalar FMA, plain loads, 4 CTA/SM occupancy) +
//  - deferred value reduction: only the gate is warp-reduced per node (5 shfl),
//    per-lane value partials are scaled by e and reduced once per segment flush
//  - x2 unroll, 4 LDG.128 batched up front, interleaved butterfly chains
//  - one boundary check per pair (ids sorted -> seg[n+1]==cur covers both)
//
// Inputs (metadata order):
//   d_in[0] states  float32 [N, 256]
//   d_in[1] seg_ids int32   [N]   (sorted)
//   d_in[2] Wg float32 [256,1]   d_in[3] bg float32 [1]
//   d_in[4] Wo float32 [256,2]   d_in[5] bo float32 [2]
// Output: float32 [B, 2], B = out_size/2

#define NBLOCKS  592
#define NTHREADS 256
#define MAXB     1024

__device__ float g_accS [MAXB];
__device__ float g_accV0[MAXB];
__device__ float g_accV1[MAXB];

__global__ void ga_zero(int B) {
    int i = blockIdx.x * blockDim.x + threadIdx.x;
    if (i < B) {
        g_accS [i] = 0.0f;
        g_accV0[i] = 0.0f;
        g_accV1[i] = 0.0f;
    }
}

__global__ __launch_bounds__(NTHREADS) void ga_main(
    const float* __restrict__ states,
    const int*   __restrict__ seg,
    const float* __restrict__ Wg,
    const float* __restrict__ bg,
    const float* __restrict__ Wo,
    const float* __restrict__ bo,
    int N)
{
    const int lane   = threadIdx.x & 31;
    const int gwarp  = (blockIdx.x * blockDim.x + threadIdx.x) >> 5;
    const int nwarps = (gridDim.x * blockDim.x) >> 5;
    const int chunk  = (N + nwarps - 1) / nwarps;
    const int start  = gwarp * chunk;
    const int end    = min(start + chunk, N);
    if (start >= end) return;

    // Per-lane slice of the weight vectors: columns [lane*8, lane*8+8)
    const int c0 = lane * 8;
    float wg[8], wo0[8], wo1[8];
#pragma unroll
    for (int j = 0; j < 8; j++) {
        wg [j] = Wg[c0 + j];
        wo0[j] = Wo[(c0 + j) * 2 + 0];
        wo1[j] = Wo[(c0 + j) * 2 + 1];
    }
    const float bgv = bg[0];
    const float bo0 = bo[0];
    const float bo1 = bo[1];

    const float4* base = reinterpret_cast<const float4*>(states);

    int   cur = seg[start];
    float aS  = 0.0f;                 // sum of e (lane-uniform)
    float aV0 = 0.0f, aV1 = 0.0f;     // per-lane partial sums of e * p_lane

    // Flush: reduce per-lane value partials across the warp, then atomic.
    //   sum_n e_n*(p0_n + bo0) = warp_sum(aV0) + bo0 * aS
#define FLUSH(SEGID)                                                        \
    do {                                                                    \
        float _v0 = aV0, _v1 = aV1;                                         \
        _Pragma("unroll")                                                   \
        for (int _o = 16; _o; _o >>= 1) {                                   \
            _v0 += __shfl_xor_sync(0xFFFFFFFFu, _v0, _o);                   \
            _v1 += __shfl_xor_sync(0xFFFFFFFFu, _v1, _o);                   \
        }                                                                   \
        if (lane == 0) {                                                    \
            atomicAdd(&g_accS [SEGID], aS);                                 \
            atomicAdd(&g_accV0[SEGID], fmaf(bo0, aS, _v0));                 \
            atomicAdd(&g_accV1[SEGID], fmaf(bo1, aS, _v1));                 \
        }                                                                   \
        aS = 0.0f; aV0 = 0.0f; aV1 = 0.0f;                                  \
    } while (0)

    int n = start;

    // ---- main loop: 2 nodes/iter, all 4 row loads batched up front ----
    for (; n + 2 <= end; n += 2) {
        const float4* r0 = base + (size_t)(n + 0) * 64 + lane * 2;
        const float4* r1 = base + (size_t)(n + 1) * 64 + lane * 2;
        float4 xa0 = r0[0];
        float4 xb0 = r0[1];
        float4 xa1 = r1[0];
        float4 xb1 = r1[1];
        int sv1 = seg[n + 1];   // sorted: sv1 == cur implies seg[n] == cur

        float x0[8] = {xa0.x, xa0.y, xa0.z, xa0.w, xb0.x, xb0.y, xb0.z, xb0.w};
        float x1[8] = {xa1.x, xa1.y, xa1.z, xa1.w, xb1.x, xb1.y, xb1.z, xb1.w};

        float g0 = 0.f, p00 = 0.f, p10 = 0.f;
        float g1 = 0.f, p01 = 0.f, p11 = 0.f;
#pragma unroll
        for (int j = 0; j < 8; j++) {
            g0  = fmaf(x0[j], wg [j], g0);
            g1  = fmaf(x1[j], wg [j], g1);
            p00 = fmaf(x0[j], wo0[j], p00);
            p01 = fmaf(x1[j], wo0[j], p01);
            p10 = fmaf(x0[j], wo1[j], p10);
            p11 = fmaf(x1[j], wo1[j], p11);
        }

        // Two independent butterfly chains, interleaved (only the gates)
#pragma unroll
        for (int off = 16; off; off >>= 1) {
            g0 += __shfl_xor_sync(0xFFFFFFFFu, g0, off);
            g1 += __shfl_xor_sync(0xFFFFFFFFu, g1, off);
        }

        float e0 = __expf(g0 + bgv);
        float e1 = __expf(g1 + bgv);

        if (sv1 != cur) {                    // rare: <=127 times total
            int sv0 = seg[n];
            if (sv0 != cur) { FLUSH(cur); cur = sv0; }
            aS += e0;
            aV0 = fmaf(e0, p00, aV0);
            aV1 = fmaf(e0, p10, aV1);
            if (sv1 != cur) { FLUSH(cur); cur = sv1; }
            aS += e1;
            aV0 = fmaf(e1, p01, aV0);
            aV1 = fmaf(e1, p11, aV1);
        } else {                             // hot path
            aS += e0 + e1;
            aV0 = fmaf(e0, p00, fmaf(e1, p01, aV0));
            aV1 = fmaf(e0, p10, fmaf(e1, p11, aV1));
        }
    }

    // ---- tail (at most 1 node) ----
    for (; n < end; n++) {
        const float4* row = base + (size_t)n * 64 + lane * 2;
        float4 xa = row[0];
        float4 xb = row[1];
        int s = seg[n];

        float x[8] = {xa.x, xa.y, xa.z, xa.w, xb.x, xb.y, xb.z, xb.w};
        float g = 0.f, p0 = 0.f, p1 = 0.f;
#pragma unroll
        for (int j = 0; j < 8; j++) {
            g  = fmaf(x[j], wg [j], g);
            p0 = fmaf(x[j], wo0[j], p0);
            p1 = fmaf(x[j], wo1[j], p1);
        }
#pragma unroll
        for (int off = 16; off; off >>= 1)
            g += __shfl_xor_sync(0xFFFFFFFFu, g, off);

        float e = __expf(g + bgv);
        if (s != cur) { FLUSH(cur); cur = s; }
        aS += e;
        aV0 = fmaf(e, p0, aV0);
        aV1 = fmaf(e, p1, aV1);
    }

    FLUSH(cur);
#undef FLUSH
}

__global__ void ga_finalize(float* __restrict__ out, int B) {
    int b = blockIdx.x * blockDim.x + threadIdx.x;
    if (b < B) {
        float d = g_accS[b] + 1e-16f;
        out[2 * b + 0] = g_accV0[b] / d;
        out[2 * b + 1] = g_accV1[b] / d;
    }
}

extern "C" void kernel_launch(void* const* d_in, const int* in_sizes, int n_in,
                              void* d_out, int out_size)
{
    const float* states = (const float*)d_in[0];
    const int*   seg    = (const int*)  d_in[1];
    const float* Wg     = (const float*)d_in[2];
    const float* bg     = (const float*)d_in[3];
    const float* Wo     = (const float*)d_in[4];
    const float* bo     = (const float*)d_in[5];
    float*       out    = (float*)d_out;

    const int N = in_sizes[1];
    const int B = out_size / 2;

    ga_zero<<<(B + 255) / 256, 256>>>(B);
    ga_main<<<NBLOCKS, NTHREADS>>>(states, seg, Wg, bg, Wo, bo, N);
    ga_finalize<<<(B + 255) / 256, 256>>>(out, B);
}